// round 1
// baseline (speedup 1.0000x reference)
#include <cuda_runtime.h>
#include <cstdint>

// Problem constants
constexpr int Bb   = 64;
constexpr int IC   = 32;
constexpr int PC   = 128;
constexpr int RC   = 32;
constexpr int OC   = 128;
constexpr int Hh   = 96;
constexpr int Ww   = 320;
constexpr int Npts = 2048;
constexpr float EPS = 1e-5f;

constexpr int TILE    = 32;           // points per block
constexpr int THREADS = 256;
constexpr int TILES_PER_B = Npts / TILE;   // 64
constexpr int GRID = Bb * TILES_PER_B;     // 4096

// Shared memory layout (in floats)
constexpr int OFF_CAT = 0;                       // [256][32] concat: rows 0..127 pf, 128..255 img_new
constexpr int OFF_IMG = OFF_CAT + 2 * PC * TILE; // [32][32] gathered img features
constexpr int OFF_T   = OFF_IMG + IC * TILE;     // [32][32] tanh(ri+rp)
constexpr int OFF_WF1 = OFF_T + RC * TILE;       // 32x32
constexpr int OFF_WF2 = OFF_WF1 + RC * IC;       // 32x128
constexpr int OFF_WIA = OFF_WF2 + RC * PC;       // 128x32
constexpr int OFF_SC1 = OFF_WIA + PC * IC;       // 128
constexpr int OFF_SH1 = OFF_SC1 + PC;            // 128
constexpr int OFF_SC2 = OFF_SH1 + PC;            // 128
constexpr int OFF_SH2 = OFF_SC2 + OC;            // 128
constexpr int OFF_ATT = OFF_SH2 + OC;            // 32
constexpr int OFF_BR  = OFF_ATT + TILE;          // 32
constexpr int OFF_W3  = OFF_BR + RC;             // 32
constexpr int OFF_GX  = OFF_W3 + RC;             // 32
constexpr int OFF_GY  = OFF_GX + TILE;           // 32
constexpr int OFF_B3  = OFF_GY + TILE;           // 4
constexpr int SMEM_FLOATS = OFF_B3 + 4;
constexpr int SMEM_BYTES  = SMEM_FLOATS * 4;     // ~80.5 KB

#define DEV __device__ __forceinline__

// ---- packed f32x2 helpers (Blackwell FFMA2; ptxas never emits from C++) ----
DEV unsigned long long pk2(float v) {
    unsigned long long r;
    asm("mov.b64 %0, {%1, %1};" : "=l"(r) : "f"(v));
    return r;
}
DEV unsigned long long f2fma(unsigned long long a, unsigned long long b, unsigned long long c) {
    unsigned long long d;
    asm("fma.rn.f32x2 %0, %1, %2, %3;" : "=l"(d) : "l"(a), "l"(b), "l"(c));
    return d;
}
DEV float2 upk(unsigned long long a) {
    float2 f;
    asm("mov.b64 {%0, %1}, %2;" : "=f"(f.x), "=f"(f.y) : "l"(a));
    return f;
}

extern __shared__ float sm[];

__global__ void __launch_bounds__(THREADS, 2)
fused_rcnn_kernel(const float* __restrict__ img_map,   // (B,IC,H,W)
                  const float* __restrict__ xy,        // (B,N,2)
                  const float* __restrict__ pf,        // (B,PC,N)
                  const float* __restrict__ W_ia,      // (PC,IC)
                  const float* __restrict__ b_ia,      // (PC)
                  const float* __restrict__ g1, const float* __restrict__ bt1,
                  const float* __restrict__ m1, const float* __restrict__ v1,
                  const float* __restrict__ Wf1,       // (RC,IC)
                  const float* __restrict__ bf1,       // (RC)
                  const float* __restrict__ Wf2,       // (RC,PC)
                  const float* __restrict__ bf2,       // (RC)
                  const float* __restrict__ Wf3,       // (1,RC)
                  const float* __restrict__ bf3,       // (1)
                  const float* __restrict__ W_fuse,    // (OC,2*PC)
                  const float* __restrict__ b_fuse,    // (OC)
                  const float* __restrict__ g2, const float* __restrict__ bt2,
                  const float* __restrict__ m2, const float* __restrict__ v2,
                  float* __restrict__ out)             // (B,OC,N)
{
    const int tid = threadIdx.x;
    const int blk = blockIdx.x;
    const int b   = blk / TILES_PER_B;
    const int n0  = (blk % TILES_PER_B) * TILE;

    float* s_cat = sm + OFF_CAT;
    float* s_img = sm + OFF_IMG;
    float* s_t   = sm + OFF_T;
    float* s_Wf1 = sm + OFF_WF1;
    float* s_Wf2 = sm + OFF_WF2;
    float* s_Wia = sm + OFF_WIA;
    float* s_sc1 = sm + OFF_SC1;
    float* s_sh1 = sm + OFF_SH1;
    float* s_sc2 = sm + OFF_SC2;
    float* s_sh2 = sm + OFF_SH2;
    float* s_att = sm + OFF_ATT;
    float* s_br  = sm + OFF_BR;
    float* s_w3  = sm + OFF_W3;
    float* s_gx  = sm + OFF_GX;
    float* s_gy  = sm + OFF_GY;
    float* s_b3  = sm + OFF_B3;

    // ---------------- Phase 0: cooperative loads ----------------
    // point_feas tile -> cat rows [0,128): (128 rows x 32 cols) = 1024 float4
    for (int i = tid; i < PC * TILE / 4; i += THREADS) {
        int c = i >> 3, q = i & 7;
        float4 v = __ldg((const float4*)(pf + (size_t)(b * PC + c) * Npts + n0) + q);
        *(float4*)(s_cat + c * TILE + q * 4) = v;
    }
    for (int i = tid; i < RC * IC / 4; i += THREADS)
        ((float4*)s_Wf1)[i] = __ldg((const float4*)Wf1 + i);
    for (int i = tid; i < RC * PC / 4; i += THREADS)
        ((float4*)s_Wf2)[i] = __ldg((const float4*)Wf2 + i);
    for (int i = tid; i < PC * IC / 4; i += THREADS)
        ((float4*)s_Wia)[i] = __ldg((const float4*)W_ia + i);

    if (tid < PC) {
        float s1 = g1[tid] * rsqrtf(v1[tid] + EPS);
        s_sc1[tid] = s1;
        s_sh1[tid] = (b_ia[tid] - m1[tid]) * s1 + bt1[tid];
        float s2 = g2[tid] * rsqrtf(v2[tid] + EPS);
        s_sc2[tid] = s2;
        s_sh2[tid] = (b_fuse[tid] - m2[tid]) * s2 + bt2[tid];
    } else if (tid < PC + RC) {
        int r = tid - PC;
        s_br[r] = bf1[r] + bf2[r];
        s_w3[r] = Wf3[r];
    } else if (tid == PC + RC) {
        s_b3[0] = bf3[0];
    } else if (tid >= THREADS - TILE) {
        int pt = tid - (THREADS - TILE);
        float x = xy[(size_t)(b * Npts + n0 + pt) * 2 + 0];
        float y = xy[(size_t)(b * Npts + n0 + pt) * 2 + 1];
        s_gx[pt] = ((x + 1.0f) * (float)Ww - 1.0f) * 0.5f;
        s_gy[pt] = ((y + 1.0f) * (float)Hh - 1.0f) * 0.5f;
    }
    __syncthreads();

    // ---------------- Phase 1: bilinear gather (IC x TILE) ----------------
    for (int i = tid; i < IC * TILE; i += THREADS) {
        int c = i >> 5, pt = i & 31;
        float ix = s_gx[pt], iy = s_gy[pt];
        float fx0 = floorf(ix), fy0 = floorf(iy);
        int x0 = (int)fx0, y0 = (int)fy0;
        float wx1 = ix - fx0, wy1 = iy - fy0;
        float wx0 = 1.0f - wx1, wy0 = 1.0f - wy1;
        const float* base = img_map + (size_t)(b * IC + c) * (Hh * Ww);
        bool x0v = (x0 >= 0) && (x0 < Ww);
        bool x1v = (x0 + 1 >= 0) && (x0 + 1 < Ww);
        bool y0v = (y0 >= 0) && (y0 < Hh);
        bool y1v = (y0 + 1 >= 0) && (y0 + 1 < Hh);
        float v = 0.0f;
        if (y0v) {
            const float* r0p = base + (size_t)y0 * Ww;
            if (x0v) v += wx0 * wy0 * __ldg(r0p + x0);
            if (x1v) v += wx1 * wy0 * __ldg(r0p + x0 + 1);
        }
        if (y1v) {
            const float* r1p = base + (size_t)(y0 + 1) * Ww;
            if (x0v) v += wx0 * wy1 * __ldg(r1p + x0);
            if (x1v) v += wx1 * wy1 * __ldg(r1p + x0 + 1);
        }
        s_img[c * TILE + pt] = v;
    }
    __syncthreads();

    const int ocg = tid >> 3;          // 0..31
    const int pt0 = (tid & 7) * 4;     // 0,4,..,28

    // ---------------- Phase 2: ri + rp -> tanh ----------------
    {
        int r = ocg;
        float a0 = 0.f, a1 = 0.f, a2 = 0.f, a3 = 0.f;
        #pragma unroll
        for (int k = 0; k < IC; k++) {
            float w = s_Wf1[r * IC + k];
            float4 f = *(const float4*)(s_img + k * TILE + pt0);
            a0 += w * f.x; a1 += w * f.y; a2 += w * f.z; a3 += w * f.w;
        }
        #pragma unroll 8
        for (int k = 0; k < PC; k++) {
            float w = s_Wf2[r * PC + k];
            float4 f = *(const float4*)(s_cat + k * TILE + pt0);
            a0 += w * f.x; a1 += w * f.y; a2 += w * f.z; a3 += w * f.w;
        }
        float bb = s_br[r];
        s_t[r * TILE + pt0 + 0] = tanhf(a0 + bb);
        s_t[r * TILE + pt0 + 1] = tanhf(a1 + bb);
        s_t[r * TILE + pt0 + 2] = tanhf(a2 + bb);
        s_t[r * TILE + pt0 + 3] = tanhf(a3 + bb);
    }
    __syncthreads();

    // ---------------- Phase 3: attention scalar ----------------
    if (tid < TILE) {
        float s = 0.f;
        #pragma unroll
        for (int r = 0; r < RC; r++) s += s_w3[r] * s_t[r * TILE + tid];
        s += s_b3[0];
        s_att[tid] = 1.0f / (1.0f + expf(-s));
    }
    __syncthreads();

    // ---------------- Phase 4: img_new = relu(bn1(W_ia @ img)) * att ----------------
    {
        int oc0 = ocg * 4;
        unsigned long long a01[4] = {0, 0, 0, 0};
        unsigned long long a23[4] = {0, 0, 0, 0};
        #pragma unroll
        for (int k = 0; k < IC; k++) {
            ulonglong2 cv = *(const ulonglong2*)(s_img + k * TILE + pt0);
            #pragma unroll
            for (int i = 0; i < 4; i++) {
                unsigned long long wb = pk2(s_Wia[(oc0 + i) * IC + k]);
                a01[i] = f2fma(wb, cv.x, a01[i]);
                a23[i] = f2fma(wb, cv.y, a23[i]);
            }
        }
        float4 attv = *(const float4*)(s_att + pt0);
        #pragma unroll
        for (int i = 0; i < 4; i++) {
            float sc = s_sc1[oc0 + i], sh = s_sh1[oc0 + i];
            float2 p01 = upk(a01[i]);
            float2 p23 = upk(a23[i]);
            float4 o;
            o.x = fmaxf(p01.x * sc + sh, 0.f) * attv.x;
            o.y = fmaxf(p01.y * sc + sh, 0.f) * attv.y;
            o.z = fmaxf(p23.x * sc + sh, 0.f) * attv.z;
            o.w = fmaxf(p23.y * sc + sh, 0.f) * attv.w;
            *(float4*)(s_cat + (PC + oc0 + i) * TILE + pt0) = o;
        }
    }
    __syncthreads();

    // ---------------- Phase 5: fuse GEMM (128 x 256) + bn2 + relu ----------------
    {
        int oc0 = ocg * 4;
        unsigned long long a01[4] = {0, 0, 0, 0};
        unsigned long long a23[4] = {0, 0, 0, 0};
        const float* wp0 = W_fuse + (size_t)(oc0 + 0) * (2 * PC);
        const float* wp1 = W_fuse + (size_t)(oc0 + 1) * (2 * PC);
        const float* wp2 = W_fuse + (size_t)(oc0 + 2) * (2 * PC);
        const float* wp3 = W_fuse + (size_t)(oc0 + 3) * (2 * PC);
        #pragma unroll 2
        for (int k = 0; k < 2 * PC; k += 4) {
            float4 w0 = __ldg((const float4*)(wp0 + k));
            float4 w1 = __ldg((const float4*)(wp1 + k));
            float4 w2 = __ldg((const float4*)(wp2 + k));
            float4 w3 = __ldg((const float4*)(wp3 + k));
            ulonglong2 c0 = *(const ulonglong2*)(s_cat + (k + 0) * TILE + pt0);
            ulonglong2 c1 = *(const ulonglong2*)(s_cat + (k + 1) * TILE + pt0);
            ulonglong2 c2 = *(const ulonglong2*)(s_cat + (k + 2) * TILE + pt0);
            ulonglong2 c3 = *(const ulonglong2*)(s_cat + (k + 3) * TILE + pt0);

            {
                unsigned long long bb;
                bb = pk2(w0.x); a01[0] = f2fma(bb, c0.x, a01[0]); a23[0] = f2fma(bb, c0.y, a23[0]);
                bb = pk2(w0.y); a01[0] = f2fma(bb, c1.x, a01[0]); a23[0] = f2fma(bb, c1.y, a23[0]);
                bb = pk2(w0.z); a01[0] = f2fma(bb, c2.x, a01[0]); a23[0] = f2fma(bb, c2.y, a23[0]);
                bb = pk2(w0.w); a01[0] = f2fma(bb, c3.x, a01[0]); a23[0] = f2fma(bb, c3.y, a23[0]);
            }
            {
                unsigned long long bb;
                bb = pk2(w1.x); a01[1] = f2fma(bb, c0.x, a01[1]); a23[1] = f2fma(bb, c0.y, a23[1]);
                bb = pk2(w1.y); a01[1] = f2fma(bb, c1.x, a01[1]); a23[1] = f2fma(bb, c1.y, a23[1]);
                bb = pk2(w1.z); a01[1] = f2fma(bb, c2.x, a01[1]); a23[1] = f2fma(bb, c2.y, a23[1]);
                bb = pk2(w1.w); a01[1] = f2fma(bb, c3.x, a01[1]); a23[1] = f2fma(bb, c3.y, a23[1]);
            }
            {
                unsigned long long bb;
                bb = pk2(w2.x); a01[2] = f2fma(bb, c0.x, a01[2]); a23[2] = f2fma(bb, c0.y, a23[2]);
                bb = pk2(w2.y); a01[2] = f2fma(bb, c1.x, a01[2]); a23[2] = f2fma(bb, c1.y, a23[2]);
                bb = pk2(w2.z); a01[2] = f2fma(bb, c2.x, a01[2]); a23[2] = f2fma(bb, c2.y, a23[2]);
                bb = pk2(w2.w); a01[2] = f2fma(bb, c3.x, a01[2]); a23[2] = f2fma(bb, c3.y, a23[2]);
            }
            {
                unsigned long long bb;
                bb = pk2(w3.x); a01[3] = f2fma(bb, c0.x, a01[3]); a23[3] = f2fma(bb, c0.y, a23[3]);
                bb = pk2(w3.y); a01[3] = f2fma(bb, c1.x, a01[3]); a23[3] = f2fma(bb, c1.y, a23[3]);
                bb = pk2(w3.z); a01[3] = f2fma(bb, c2.x, a01[3]); a23[3] = f2fma(bb, c2.y, a23[3]);
                bb = pk2(w3.w); a01[3] = f2fma(bb, c3.x, a01[3]); a23[3] = f2fma(bb, c3.y, a23[3]);
            }
        }
        #pragma unroll
        for (int i = 0; i < 4; i++) {
            int oc = oc0 + i;
            float sc = s_sc2[oc], sh = s_sh2[oc];
            float2 p01 = upk(a01[i]);
            float2 p23 = upk(a23[i]);
            float4 o;
            o.x = fmaxf(p01.x * sc + sh, 0.f);
            o.y = fmaxf(p01.y * sc + sh, 0.f);
            o.z = fmaxf(p23.x * sc + sh, 0.f);
            o.w = fmaxf(p23.y * sc + sh, 0.f);
            *(float4*)(out + (size_t)(b * OC + oc) * Npts + n0 + pt0) = o;
        }
    }
}

extern "C" void kernel_launch(void* const* d_in, const int* in_sizes, int n_in,
                              void* d_out, int out_size) {
    (void)in_sizes; (void)n_in; (void)out_size;
    const float* img_map = (const float*)d_in[0];
    const float* xy      = (const float*)d_in[1];
    const float* pf      = (const float*)d_in[2];
    const float* W_ia    = (const float*)d_in[3];
    const float* b_ia    = (const float*)d_in[4];
    const float* g1      = (const float*)d_in[5];
    const float* bt1     = (const float*)d_in[6];
    const float* m1      = (const float*)d_in[7];
    const float* v1      = (const float*)d_in[8];
    const float* Wf1     = (const float*)d_in[9];
    const float* bf1     = (const float*)d_in[10];
    const float* Wf2     = (const float*)d_in[11];
    const float* bf2     = (const float*)d_in[12];
    const float* Wf3     = (const float*)d_in[13];
    const float* bf3     = (const float*)d_in[14];
    const float* W_fuse  = (const float*)d_in[15];
    const float* b_fuse  = (const float*)d_in[16];
    const float* g2      = (const float*)d_in[17];
    const float* bt2     = (const float*)d_in[18];
    const float* m2      = (const float*)d_in[19];
    const float* v2      = (const float*)d_in[20];
    float* out = (float*)d_out;

    cudaFuncSetAttribute(fused_rcnn_kernel,
                         cudaFuncAttributeMaxDynamicSharedMemorySize, SMEM_BYTES);

    fused_rcnn_kernel<<<GRID, THREADS, SMEM_BYTES>>>(
        img_map, xy, pf, W_ia, b_ia, g1, bt1, m1, v1,
        Wf1, bf1, Wf2, bf2, Wf3, bf3,
        W_fuse, b_fuse, g2, bt2, m2, v2, out);
}